// round 10
// baseline (speedup 1.0000x reference)
#include <cuda_runtime.h>
#include <cstdint>

// ============================ helpers ============================
__device__ __forceinline__ uint32_t smem_u32(const void* p) {
    uint32_t a;
    asm("{ .reg .u64 t; cvta.to.shared.u64 t, %1; cvt.u32.u64 %0, t; }" : "=r"(a) : "l"(p));
    return a;
}
__device__ __forceinline__ unsigned short f2bf(float f) {
    unsigned short r; asm("cvt.rn.bf16.f32 %0, %1;" : "=h"(r) : "f"(f)); return r;
}
__device__ __forceinline__ float bf2f(unsigned short u) {
    return __uint_as_float(((uint32_t)u) << 16);
}
// pack two floats to bf16x2: a -> lower half, b -> upper half
__device__ __forceinline__ uint32_t packbf(float a, float b) {
    uint32_t r; asm("cvt.rn.bf16x2.f32 %0, %1, %2;" : "=r"(r) : "f"(b), "f"(a)); return r;
}

#define LDM4(r, addr) \
    asm volatile("ldmatrix.sync.aligned.m8n8.x4.shared.b16 {%0,%1,%2,%3}, [%4];" \
        : "=r"((r)[0]), "=r"((r)[1]), "=r"((r)[2]), "=r"((r)[3]) : "r"(addr))

#define LDM4T(r, addr) \
    asm volatile("ldmatrix.sync.aligned.m8n8.x4.trans.shared.b16 {%0,%1,%2,%3}, [%4];" \
        : "=r"((r)[0]), "=r"((r)[1]), "=r"((r)[2]), "=r"((r)[3]) : "r"(addr))

#define MMA_BF16(c, a, b0, b1) \
    asm volatile("mma.sync.aligned.m16n8k16.row.col.f32.bf16.bf16.f32 " \
        "{%0,%1,%2,%3}, {%4,%5,%6,%7}, {%8,%9}, {%0,%1,%2,%3};" \
        : "+f"((c)[0]), "+f"((c)[1]), "+f"((c)[2]), "+f"((c)[3]) \
        : "r"((a)[0]), "r"((a)[1]), "r"((a)[2]), "r"((a)[3]), "r"(b0), "r"(b1))

#define CP_COMMIT() asm volatile("cp.async.commit_group;" ::: "memory")
#define CP_WAIT0()  asm volatile("cp.async.wait_group 0;" ::: "memory")
__device__ __forceinline__ void cp16(uint32_t dst_smem, const void* src) {
    asm volatile("cp.async.cg.shared.global [%0], [%1], 16;"
        :: "r"(dst_smem), "l"(__cvta_generic_to_global(src)) : "memory");
}

// ============================ constants ============================
constexpr int WN  = 49;
constexpr int D   = 128;
constexpr int D3  = 384;
constexpr float SCALE = 0.17677669529663687f;

// prepacked weights: 8 chunks (6 qkv + 2 wout), each [hi 18432 | lo 18432]
// layout per half: k (0..127) * 144 + n_local (0..63) * 2
__device__ unsigned char g_wpk[8][36864];

// fused-kernel smem layout (bytes)
constexpr int F_AH   = 0;        // x / attn-out hi  [64 r][272]
constexpr int F_AL   = 17408;
constexpr int F_QH   = 34816;    // q hi [64 r][272]
constexpr int F_QL   = 52224;
constexpr int F_KH   = 69632;    // k^T hi [128 d][144]
constexpr int F_KL   = 88064;
constexpr int F_VH   = 106496;   // v hi [64 r][272]
constexpr int F_VL   = 123904;
constexpr int F_B    = 141312;   // W chunk ping-pong, 2 x [hi|lo] 36864
constexpr int F_BIAS = 215040;   // 676 floats
constexpr int F_TOTAL = 217744;

// ======================= weight prepack kernel =======================
__global__ void prepack_w(const float* __restrict__ wqkv,
                          const float* __restrict__ wout)
{
    int idx = blockIdx.x * 256 + threadIdx.x;
    if (idx < 128 * 384) {
        int k = idx / 384, n = idx - (idx / 384) * 384;
        float v = wqkv[idx];
        unsigned short h = f2bf(v), l = f2bf(v - bf2f(h));
        int c = n >> 6, nn = n & 63;
        *(unsigned short*)(g_wpk[c] + k * 144 + nn * 2) = h;
        *(unsigned short*)(g_wpk[c] + 18432 + k * 144 + nn * 2) = l;
    } else if (idx < 128 * 384 + 128 * 128) {
        int i2 = idx - 128 * 384;
        int k = i2 >> 7, n = i2 & 127;
        float v = wout[i2];
        unsigned short h = f2bf(v), l = f2bf(v - bf2f(h));
        int c = 6 + (n >> 6), nn = n & 63;
        *(unsigned short*)(g_wpk[c] + k * 144 + nn * 2) = h;
        *(unsigned short*)(g_wpk[c] + 18432 + k * 144 + nn * 2) = l;
    }
}

// ============ split-bf16 pair store (hi + residual lo) ============
__device__ __forceinline__ void store_sp(char* smc, int baseH, int baseL,
                                         int off, float a, float b) {
    uint32_t hp = packbf(a, b);
    float ra = a - __uint_as_float(hp << 16);
    float rb = b - __uint_as_float(hp & 0xFFFF0000u);
    *(uint32_t*)(smc + baseH + off) = hp;
    *(uint32_t*)(smc + baseL + off) = packbf(ra, rb);
}
__device__ __forceinline__ void store_k(char* smc, int d, int r, float v) {
    unsigned short h = f2bf(v);
    *(unsigned short*)(smc + F_KH + d * 144 + r * 2) = h;
    *(unsigned short*)(smc + F_KL + d * 144 + r * 2) = f2bf(v - bf2f(h));
}

__device__ __forceinline__ void prefetch_w(uint32_t sb, int buf, int c, int t) {
    const unsigned char* src = g_wpk[c];
    uint32_t dst = sb + F_B + buf * 36864;
#pragma unroll
    for (int i = t; i < 2304; i += 256)
        cp16(dst + i * 16, src + i * 16);
    CP_COMMIT();
}

// ========================= fused window kernel =========================
__global__ __launch_bounds__(256, 1)
void fused_win(const float* __restrict__ x, const float* __restrict__ btab,
               float* __restrict__ out)
{
    extern __shared__ char smc[];
    const uint32_t sb = smem_u32(smc);
    const int t = threadIdx.x;
    const size_t win = blockIdx.x;
    const float* xw = x + win * (size_t)(WN * D);
    float* bias_s = (float*)(smc + F_BIAS);

    const int w     = t >> 5;
    const int lane  = t & 31;
    const int wm    = w & 3;          // m-tile (16 rows), m = 64
    const int wn    = w >> 2;         // n 32-col half of 64-chunk
    const int lrow  = lane & 15;
    const int lhalf = lane >> 4;
    const int qrow  = lane >> 2;
    const int qt2   = (lane & 3) << 1;

    // kick off W chunk 0 prefetch immediately
    prefetch_w(sb, 0, 0, t);

    // ---- zero A (x pad rows must be 0), stage bias ----
    uint4 z4 = make_uint4(0u, 0u, 0u, 0u);
    for (int i = t; i < 2176; i += 256) ((uint4*)smc)[i] = z4;  // 34816 B
    for (int i = t; i < 676; i += 256) bias_s[i] = btab[i];

    // ---- stage x (49 x 128 f32) -> split-bf16 A ----
    for (int idx4 = t; idx4 < 1568; idx4 += 256) {   // 49 rows x 32 float4
        int r  = idx4 >> 5;
        int c4 = (idx4 & 31) << 2;
        float4 v = *(const float4*)(xw + r * D + c4);
        float vv[4] = {v.x, v.y, v.z, v.w};
        unsigned short hh[4], ll[4];
#pragma unroll
        for (int e = 0; e < 4; e++) {
            hh[e] = f2bf(vv[e]); ll[e] = f2bf(vv[e] - bf2f(hh[e]));
        }
        int off = r * 272 + c4 * 2;
        *(uint2*)(smc + F_AH + off) = make_uint2(
            (uint32_t)hh[0] | ((uint32_t)hh[1] << 16),
            (uint32_t)hh[2] | ((uint32_t)hh[3] << 16));
        *(uint2*)(smc + F_AL + off) = make_uint2(
            (uint32_t)ll[0] | ((uint32_t)ll[1] << 16),
            (uint32_t)ll[2] | ((uint32_t)ll[3] << 16));
    }

    // ================= Phase 1: QKV GEMM, 6 chunks of 64 cols =================
#pragma unroll 1
    for (int c = 0; c < 6; c++) {
        CP_WAIT0();
        __syncthreads();
        if (c < 5) prefetch_w(sb, (c + 1) & 1, c + 1, t);
        const uint32_t B = sb + F_B + (c & 1) * 36864;

        float acc[4][4];
#pragma unroll
        for (int j = 0; j < 4; j++)
#pragma unroll
            for (int e = 0; e < 4; e++) acc[j][e] = 0.f;

#pragma unroll
        for (int kt = 0; kt < 8; kt++) {
            uint32_t ah[4], al[4], bh[2][4], bl[2][4];
            uint32_t aoff = (uint32_t)((wm * 16 + lrow) * 272 + kt * 32 + lhalf * 16);
            LDM4(ah, sb + F_AH + aoff);
            LDM4(al, sb + F_AL + aoff);
#pragma unroll
            for (int nt = 0; nt < 2; nt++) {
                uint32_t boff = (uint32_t)((kt * 16 + lrow) * 144
                                           + (wn * 32 + nt * 16) * 2 + lhalf * 16);
                LDM4T(bh[nt], B + boff);
                LDM4T(bl[nt], B + 18432 + boff);
            }
#pragma unroll
            for (int j = 0; j < 4; j++)
                MMA_BF16(acc[j], ah, bh[j >> 1][2 * (j & 1)], bh[j >> 1][2 * (j & 1) + 1]);
#pragma unroll
            for (int j = 0; j < 4; j++)
                MMA_BF16(acc[j], ah, bl[j >> 1][2 * (j & 1)], bl[j >> 1][2 * (j & 1) + 1]);
#pragma unroll
            for (int j = 0; j < 4; j++)
                MMA_BF16(acc[j], al, bh[j >> 1][2 * (j & 1)], bh[j >> 1][2 * (j & 1) + 1]);
        }

        // epilogue -> q / k^T / v smem (split bf16)
        const int r0 = wm * 16 + qrow, r1 = r0 + 8;
        const int nc0 = c * 64 + wn * 32;
#pragma unroll
        for (int j = 0; j < 4; j++) {
            int col = nc0 + j * 8 + qt2;
            if (c < 2) {              // q: dims 0..127, row-major
                store_sp(smc, F_QH, F_QL, r0 * 272 + col * 2, acc[j][0], acc[j][1]);
                store_sp(smc, F_QH, F_QL, r1 * 272 + col * 2, acc[j][2], acc[j][3]);
            } else if (c < 4) {       // k: transposed [d][token]
                int d = col - 128;
                store_k(smc, d,     r0, acc[j][0]);
                store_k(smc, d + 1, r0, acc[j][1]);
                store_k(smc, d,     r1, acc[j][2]);
                store_k(smc, d + 1, r1, acc[j][3]);
            } else {                  // v: dims 0..127, row-major
                int d = col - 256;
                store_sp(smc, F_VH, F_VL, r0 * 272 + d * 2, acc[j][0], acc[j][1]);
                store_sp(smc, F_VH, F_VL, r1 * 272 + d * 2, acc[j][2], acc[j][3]);
            }
        }
    }
    __syncthreads();

    // prefetch Wout chunk 0 (overlaps attention)
    prefetch_w(sb, 0, 6, t);

    // ================= Phase 2: attention (tensor core) =================
#pragma unroll 1
    for (int task = w; task < 16; task += 8) {
        const int h  = task >> 2;
        const int i0 = (task & 3) << 4;

        float sc[7][4];
#pragma unroll
        for (int nt = 0; nt < 7; nt++)
#pragma unroll
            for (int e = 0; e < 4; e++) sc[nt][e] = 0.f;

#pragma unroll
        for (int kt = 0; kt < 2; kt++) {
            uint32_t ah[4], al[4], bh[4][4], bl[4][4];
            uint32_t aoff = (uint32_t)((i0 + lrow) * 272
                                       + (h * 32 + kt * 16) * 2 + lhalf * 16);
            LDM4(ah, sb + F_QH + aoff);
            LDM4(al, sb + F_QL + aoff);
#pragma unroll
            for (int g = 0; g < 4; g++) {
                uint32_t boff = (uint32_t)((h * 32 + kt * 16 + lrow) * 144
                                           + g * 32 + lhalf * 16);
                LDM4T(bh[g], sb + F_KH + boff);
                LDM4T(bl[g], sb + F_KL + boff);
            }
#pragma unroll
            for (int nt = 0; nt < 7; nt++)
                MMA_BF16(sc[nt], ah, bh[nt >> 1][2 * (nt & 1)], bh[nt >> 1][2 * (nt & 1) + 1]);
#pragma unroll
            for (int nt = 0; nt < 7; nt++)
                MMA_BF16(sc[nt], ah, bl[nt >> 1][2 * (nt & 1)], bl[nt >> 1][2 * (nt & 1) + 1]);
#pragma unroll
            for (int nt = 0; nt < 7; nt++)
                MMA_BF16(sc[nt], al, bh[nt >> 1][2 * (nt & 1)], bh[nt >> 1][2 * (nt & 1) + 1]);
        }

        // softmax in fragments (unnormalized)
        const int r0 = i0 + qrow, r1 = r0 + 8;
        const int gi0 = r0 / 7, gj0 = r0 - 7 * gi0;
        const int gi1 = r1 / 7, gj1 = r1 - 7 * gi1;
        float rs0 = 0.f, rs1 = 0.f;
#pragma unroll
        for (int nt = 0; nt < 7; nt++) {
#pragma unroll
            for (int e = 0; e < 4; e++) {
                int j = nt * 8 + qt2 + (e & 1);
                int r = (e < 2) ? r0 : r1;
                float ev = 0.f;
                if (r < 49 && j < 49) {
                    int gj2 = j / 7;
                    int gjj = j - 7 * gj2;
                    int gi = (e < 2) ? gi0 : gi1;
                    int gj = (e < 2) ? gj0 : gj1;
                    int bidx = ((gi - gj2 + 6) * 13 + (gj - gjj + 6)) * 4 + h;
                    ev = __expf(sc[nt][e] * SCALE + bias_s[bidx]);
                }
                sc[nt][e] = ev;
                if (e < 2) rs0 += ev; else rs1 += ev;
            }
        }
        rs0 += __shfl_xor_sync(0xFFFFFFFFu, rs0, 1);
        rs0 += __shfl_xor_sync(0xFFFFFFFFu, rs0, 2);
        rs1 += __shfl_xor_sync(0xFFFFFFFFu, rs1, 1);
        rs1 += __shfl_xor_sync(0xFFFFFFFFu, rs1, 2);
        const float inv0 = (r0 < 49) ? 1.f / rs0 : 0.f;
        const float inv1 = (r1 < 49) ? 1.f / rs1 : 0.f;

        // O = P V (P built in-register, split)
        float oc[4][4];
#pragma unroll
        for (int nt = 0; nt < 4; nt++)
#pragma unroll
            for (int e = 0; e < 4; e++) oc[nt][e] = 0.f;

#pragma unroll
        for (int kt2 = 0; kt2 < 4; kt2++) {
            const int lo = 2 * kt2, hi = lo + 1;
            float pe[8];
            pe[0] = sc[lo][0]; pe[1] = sc[lo][1];
            pe[2] = sc[lo][2]; pe[3] = sc[lo][3];
            if (hi < 7) {
                pe[4] = sc[hi][0]; pe[5] = sc[hi][1];
                pe[6] = sc[hi][2]; pe[7] = sc[hi][3];
            } else {
                pe[4] = pe[5] = pe[6] = pe[7] = 0.f;
            }
            uint32_t ph[4], pl[4];
#pragma unroll
            for (int g = 0; g < 4; g++) {
                float a = pe[2 * g], b = pe[2 * g + 1];
                uint32_t hp = packbf(a, b);
                float ra = a - __uint_as_float(hp << 16);
                float rb = b - __uint_as_float(hp & 0xFFFF0000u);
                ph[g] = hp;
                pl[g] = packbf(ra, rb);
            }
            uint32_t vh[2][4], vl[2][4];
#pragma unroll
            for (int g = 0; g < 2; g++) {
                uint32_t voff = (uint32_t)((kt2 * 16 + lrow) * 272
                                           + h * 64 + g * 32 + lhalf * 16);
                LDM4T(vh[g], sb + F_VH + voff);
                LDM4T(vl[g], sb + F_VL + voff);
            }
#pragma unroll
            for (int nt = 0; nt < 4; nt++)
                MMA_BF16(oc[nt], ph, vh[nt >> 1][2 * (nt & 1)], vh[nt >> 1][2 * (nt & 1) + 1]);
#pragma unroll
            for (int nt = 0; nt < 4; nt++)
                MMA_BF16(oc[nt], ph, vl[nt >> 1][2 * (nt & 1)], vl[nt >> 1][2 * (nt & 1) + 1]);
#pragma unroll
            for (int nt = 0; nt < 4; nt++)
                MMA_BF16(oc[nt], pl, vh[nt >> 1][2 * (nt & 1)], vh[nt >> 1][2 * (nt & 1) + 1]);
        }

        // store attn-out (normalized) into A buffer (split bf16)
#pragma unroll
        for (int nt = 0; nt < 4; nt++) {
            int col = h * 32 + nt * 8 + qt2;
            if (r0 < 49)
                store_sp(smc, F_AH, F_AL, r0 * 272 + col * 2,
                         oc[nt][0] * inv0, oc[nt][1] * inv0);
            if (r1 < 49)
                store_sp(smc, F_AH, F_AL, r1 * 272 + col * 2,
                         oc[nt][2] * inv1, oc[nt][3] * inv1);
        }
    }

    // ================= Phase 3: out-proj GEMM, 2 chunks =================
#pragma unroll 1
    for (int c = 0; c < 2; c++) {
        CP_WAIT0();
        __syncthreads();
        if (c == 0) prefetch_w(sb, 1, 7, t);
        const uint32_t B = sb + F_B + c * 36864;

        float acc[4][4];
#pragma unroll
        for (int j = 0; j < 4; j++)
#pragma unroll
            for (int e = 0; e < 4; e++) acc[j][e] = 0.f;

#pragma unroll
        for (int kt = 0; kt < 8; kt++) {
            uint32_t ah[4], al[4], bh[2][4], bl[2][4];
            uint32_t aoff = (uint32_t)((wm * 16 + lrow) * 272 + kt * 32 + lhalf * 16);
            LDM4(ah, sb + F_AH + aoff);
            LDM4(al, sb + F_AL + aoff);
#pragma unroll
            for (int nt = 0; nt < 2; nt++) {
                uint32_t boff = (uint32_t)((kt * 16 + lrow) * 144
                                           + (wn * 32 + nt * 16) * 2 + lhalf * 16);
                LDM4T(bh[nt], B + boff);
                LDM4T(bl[nt], B + 18432 + boff);
            }
#pragma unroll
            for (int j = 0; j < 4; j++)
                MMA_BF16(acc[j], ah, bh[j >> 1][2 * (j & 1)], bh[j >> 1][2 * (j & 1) + 1]);
#pragma unroll
            for (int j = 0; j < 4; j++)
                MMA_BF16(acc[j], ah, bl[j >> 1][2 * (j & 1)], bl[j >> 1][2 * (j & 1) + 1]);
#pragma unroll
            for (int j = 0; j < 4; j++)
                MMA_BF16(acc[j], al, bh[j >> 1][2 * (j & 1)], bh[j >> 1][2 * (j & 1) + 1]);
        }

        const int r0 = wm * 16 + qrow, r1 = r0 + 8;
#pragma unroll
        for (int j = 0; j < 4; j++) {
            int col = c * 64 + wn * 32 + j * 8 + qt2;
            if (r0 < 49)
                *(float2*)(out + (win * WN + r0) * (size_t)D + col) =
                    make_float2(acc[j][0], acc[j][1]);
            if (r1 < 49)
                *(float2*)(out + (win * WN + r1) * (size_t)D + col) =
                    make_float2(acc[j][2], acc[j][3]);
        }
    }
}

// ============================== launcher ==============================
extern "C" void kernel_launch(void* const* d_in, const int* in_sizes, int n_in,
                              void* d_out, int out_size) {
    const float* x    = (const float*)d_in[0];
    const float* wqkv = (const float*)d_in[1];
    const float* wout = (const float*)d_in[2];
    const float* btab = (const float*)d_in[3];
    float* out = (float*)d_out;

    const int n_win = in_sizes[0] / (WN * D);

    cudaFuncSetAttribute(fused_win,
                         cudaFuncAttributeMaxDynamicSharedMemorySize, F_TOTAL);

    prepack_w<<<256, 256>>>(wqkv, wout);
    fused_win<<<n_win, 256, F_TOTAL>>>(x, btab, out);
}